// round 1
// baseline (speedup 1.0000x reference)
#include <cuda_runtime.h>

#define N_NODES 50000
#define N_EDGES 800000
#define HID 128
#define OUTD 64
#define BN_EPS 1e-5f

// ---------------- scratch (device globals: allocation-free) ----------------
__device__ __align__(16) float g_deg[N_NODES];
__device__ __align__(16) float g_dinv[N_NODES];
__device__ __align__(16) float g_hp[(size_t)N_NODES * HID];   // (X@W) * dinv[row]
__device__ __align__(16) float g_agg[(size_t)N_NODES * HID];  // scatter accumulator
__device__ __align__(16) float g_act[(size_t)N_NODES * HID];  // layer activations

// ---------------- degree / dinv ----------------
__global__ void zero_deg_kernel() {
    int i = blockIdx.x * blockDim.x + threadIdx.x;
    if (i < N_NODES) g_deg[i] = 0.f;
}
__global__ void deg_kernel(const int* __restrict__ dst) {
    int e = blockIdx.x * blockDim.x + threadIdx.x;
    if (e < N_EDGES) atomicAdd(&g_deg[dst[e]], 1.0f);
}
__global__ void dinv_kernel() {
    int i = blockIdx.x * blockDim.x + threadIdx.x;
    if (i < N_NODES) g_dinv[i] = rsqrtf(1.0f + g_deg[i]);
}
__global__ void zero_agg_kernel() {
    int i = blockIdx.x * blockDim.x + threadIdx.x;
    if (i < N_NODES * HID / 4)
        reinterpret_cast<float4*>(g_agg)[i] = make_float4(0.f, 0.f, 0.f, 0.f);
}

// ---------------- GEMM: hp = (X @ W) * dinv[row] ----------------
// X: [N,K] row-major, W: [K,128]. 64 rows per block, 256 threads,
// each thread computes 4 rows x 8 cols. W staged in 32-row k-chunks so
// static shared stays <= 48KB (no func-attribute calls during capture).
template <int K, bool FROM_ACT>
__global__ __launch_bounds__(256) void gemm_scale_kernel(const float* __restrict__ Xin,
                                                          const float* __restrict__ W) {
    __shared__ float xs[64 * K];
    __shared__ float ws[32 * HID];
    const float* __restrict__ X = FROM_ACT ? (const float*)g_act : Xin;

    const int row0 = blockIdx.x * 64;
    const int nrows = min(64, N_NODES - row0);

    for (int i = threadIdx.x; i < 64 * (K / 4); i += 256) {
        int r = i / (K / 4), c = i % (K / 4);
        float4 v = make_float4(0.f, 0.f, 0.f, 0.f);
        if (r < nrows) v = reinterpret_cast<const float4*>(X + (size_t)(row0 + r) * K)[c];
        reinterpret_cast<float4*>(xs)[i] = v;
    }

    const int tx = threadIdx.x & 15;  // 16 col-groups of 8
    const int ty = threadIdx.x >> 4;  // 16 row-groups of 4
    float acc[4][8];
#pragma unroll
    for (int i = 0; i < 4; i++)
#pragma unroll
        for (int j = 0; j < 8; j++) acc[i][j] = 0.f;

    for (int kc = 0; kc < K; kc += 32) {
        __syncthreads();  // protects ws reuse (and xs fill on first pass)
        for (int i = threadIdx.x; i < 32 * HID / 4; i += 256)
            reinterpret_cast<float4*>(ws)[i] =
                reinterpret_cast<const float4*>(W + (size_t)kc * HID)[i];
        __syncthreads();
#pragma unroll 8
        for (int k = 0; k < 32; ++k) {
            float a[4];
#pragma unroll
            for (int i = 0; i < 4; i++) a[i] = xs[(ty * 4 + i) * K + kc + k];
            float4 w0 = reinterpret_cast<const float4*>(&ws[k * HID + tx * 8])[0];
            float4 w1 = reinterpret_cast<const float4*>(&ws[k * HID + tx * 8])[1];
#pragma unroll
            for (int i = 0; i < 4; i++) {
                acc[i][0] = fmaf(a[i], w0.x, acc[i][0]);
                acc[i][1] = fmaf(a[i], w0.y, acc[i][1]);
                acc[i][2] = fmaf(a[i], w0.z, acc[i][2]);
                acc[i][3] = fmaf(a[i], w0.w, acc[i][3]);
                acc[i][4] = fmaf(a[i], w1.x, acc[i][4]);
                acc[i][5] = fmaf(a[i], w1.y, acc[i][5]);
                acc[i][6] = fmaf(a[i], w1.z, acc[i][6]);
                acc[i][7] = fmaf(a[i], w1.w, acc[i][7]);
            }
        }
    }

#pragma unroll
    for (int i = 0; i < 4; i++) {
        int r = row0 + ty * 4 + i;
        if (r < N_NODES) {
            float d = g_dinv[r];
            float4 o0 = make_float4(acc[i][0] * d, acc[i][1] * d, acc[i][2] * d, acc[i][3] * d);
            float4 o1 = make_float4(acc[i][4] * d, acc[i][5] * d, acc[i][6] * d, acc[i][7] * d);
            float4* p = reinterpret_cast<float4*>(g_hp + (size_t)r * HID + tx * 8);
            p[0] = o0;
            p[1] = o1;
        }
    }
}

// ---------------- edge scatter: agg[dst] += hp[src] (warp per edge) ----------------
__global__ __launch_bounds__(256) void scatter_kernel(const int* __restrict__ src,
                                                       const int* __restrict__ dst) {
    int gw = (blockIdx.x * blockDim.x + threadIdx.x) >> 5;
    int lane = threadIdx.x & 31;
    if (gw >= N_EDGES) return;
    int s = src[gw];
    int d = dst[gw];
    float4 v = reinterpret_cast<const float4*>(g_hp + (size_t)s * HID)[lane];
    float* p = g_agg + (size_t)d * HID + lane * 4;
    asm volatile("red.global.add.v4.f32 [%0], {%1, %2, %3, %4};"
                 :: "l"(p), "f"(v.x), "f"(v.y), "f"(v.z), "f"(v.w)
                 : "memory");
}

// ---------------- epilogue: act = relu(dinv*(agg+hp)*s + c), BN folded ----------------
__global__ __launch_bounds__(256) void finalize_kernel(const float* __restrict__ b,
                                                        const float* __restrict__ g,
                                                        const float* __restrict__ be,
                                                        const float* __restrict__ m,
                                                        const float* __restrict__ v) {
    int idx = blockIdx.x * blockDim.x + threadIdx.x;  // float4 index
    if (idx >= N_NODES * HID / 4) return;
    int r = idx >> 5;          // 32 float4 per row
    int j = (idx & 31) * 4;    // channel base
    float d = g_dinv[r];
    float4 h = reinterpret_cast<const float4*>(g_hp)[idx];
    float4 a = reinterpret_cast<const float4*>(g_agg)[idx];
    float4 o;
#define BN_DO(comp, jj)                                              \
    {                                                                \
        float s = g[jj] * rsqrtf(v[jj] + BN_EPS);                    \
        float cc = fmaf(b[jj] - m[jj], s, be[jj]);                   \
        o.comp = fmaxf(fmaf(d * (h.comp + a.comp), s, cc), 0.f);     \
    }
    BN_DO(x, j) BN_DO(y, j + 1) BN_DO(z, j + 2) BN_DO(w, j + 3)
#undef BN_DO
    reinterpret_cast<float4*>(g_act)[idx] = o;
}

// ---------------- fused MLP head: out = relu(act@W1+b1)@W2 + b2 ----------------
__global__ __launch_bounds__(256) void mlp_kernel(const float* __restrict__ W1,
                                                   const float* __restrict__ b1,
                                                   const float* __restrict__ W2,
                                                   const float* __restrict__ b2,
                                                   float* __restrict__ out) {
    __shared__ float hs[64 * HID];   // input rows, then reused for t = relu(...)
    __shared__ float ws[32 * HID];   // W chunk (4096 floats; W2 chunk [64][64] same size)
    const int row0 = blockIdx.x * 64;
    const int nrows = min(64, N_NODES - row0);

    for (int i = threadIdx.x; i < 64 * (HID / 4); i += 256) {
        int r = i / 32, c = i % 32;
        float4 v = make_float4(0.f, 0.f, 0.f, 0.f);
        if (r < nrows) v = reinterpret_cast<const float4*>(g_act + (size_t)(row0 + r) * HID)[c];
        reinterpret_cast<float4*>(hs)[i] = v;
    }

    const int tx = threadIdx.x & 15;
    const int ty = threadIdx.x >> 4;

    // stage 1: t = relu(hs @ W1 + b1), 64x128
    float acc[4][8];
#pragma unroll
    for (int i = 0; i < 4; i++)
#pragma unroll
        for (int j = 0; j < 8; j++) acc[i][j] = 0.f;

    for (int kc = 0; kc < HID; kc += 32) {
        __syncthreads();
        for (int i = threadIdx.x; i < 32 * HID / 4; i += 256)
            reinterpret_cast<float4*>(ws)[i] =
                reinterpret_cast<const float4*>(W1 + (size_t)kc * HID)[i];
        __syncthreads();
#pragma unroll 8
        for (int k = 0; k < 32; ++k) {
            float a[4];
#pragma unroll
            for (int i = 0; i < 4; i++) a[i] = hs[(ty * 4 + i) * HID + kc + k];
            float4 w0 = reinterpret_cast<const float4*>(&ws[k * HID + tx * 8])[0];
            float4 w1 = reinterpret_cast<const float4*>(&ws[k * HID + tx * 8])[1];
#pragma unroll
            for (int i = 0; i < 4; i++) {
                acc[i][0] = fmaf(a[i], w0.x, acc[i][0]);
                acc[i][1] = fmaf(a[i], w0.y, acc[i][1]);
                acc[i][2] = fmaf(a[i], w0.z, acc[i][2]);
                acc[i][3] = fmaf(a[i], w0.w, acc[i][3]);
                acc[i][4] = fmaf(a[i], w1.x, acc[i][4]);
                acc[i][5] = fmaf(a[i], w1.y, acc[i][5]);
                acc[i][6] = fmaf(a[i], w1.z, acc[i][6]);
                acc[i][7] = fmaf(a[i], w1.w, acc[i][7]);
            }
        }
    }

    __syncthreads();  // everyone done reading hs before it becomes t
#pragma unroll
    for (int i = 0; i < 4; i++)
#pragma unroll
        for (int j = 0; j < 8; j++)
            hs[(ty * 4 + i) * HID + tx * 8 + j] = fmaxf(acc[i][j] + b1[tx * 8 + j], 0.f);

    // stage 2: out = t @ W2 + b2, 64x64 (tx -> 4 cols each)
    float acc2[4][4];
#pragma unroll
    for (int i = 0; i < 4; i++)
#pragma unroll
        for (int j = 0; j < 4; j++) acc2[i][j] = 0.f;

    for (int kc = 0; kc < HID; kc += 64) {
        __syncthreads();
        for (int i = threadIdx.x; i < 64 * OUTD / 4; i += 256)
            reinterpret_cast<float4*>(ws)[i] =
                reinterpret_cast<const float4*>(W2 + (size_t)kc * OUTD)[i];
        __syncthreads();
#pragma unroll 8
        for (int k = 0; k < 64; ++k) {
            float a[4];
#pragma unroll
            for (int i = 0; i < 4; i++) a[i] = hs[(ty * 4 + i) * HID + kc + k];
            float4 wv = *reinterpret_cast<const float4*>(&ws[k * OUTD + tx * 4]);
#pragma unroll
            for (int i = 0; i < 4; i++) {
                acc2[i][0] = fmaf(a[i], wv.x, acc2[i][0]);
                acc2[i][1] = fmaf(a[i], wv.y, acc2[i][1]);
                acc2[i][2] = fmaf(a[i], wv.z, acc2[i][2]);
                acc2[i][3] = fmaf(a[i], wv.w, acc2[i][3]);
            }
        }
    }

#pragma unroll
    for (int i = 0; i < 4; i++) {
        int r = row0 + ty * 4 + i;
        if (r < N_NODES) {
            float4 o = make_float4(acc2[i][0] + b2[tx * 4 + 0], acc2[i][1] + b2[tx * 4 + 1],
                                   acc2[i][2] + b2[tx * 4 + 2], acc2[i][3] + b2[tx * 4 + 3]);
            *reinterpret_cast<float4*>(out + (size_t)r * OUTD + tx * 4) = o;
        }
    }
}

// ---------------- launch ----------------
extern "C" void kernel_launch(void* const* d_in, const int* in_sizes, int n_in,
                              void* d_out, int out_size) {
    (void)in_sizes; (void)n_in; (void)out_size;
    const float* x   = (const float*)d_in[0];
    const int*   src = (const int*)d_in[1];
    const int*   dst = (const int*)d_in[2];
    const float* W0 = (const float*)d_in[3],  *b0 = (const float*)d_in[4];
    const float* g0 = (const float*)d_in[5],  *be0 = (const float*)d_in[6];
    const float* m0 = (const float*)d_in[7],  *v0 = (const float*)d_in[8];
    const float* W1 = (const float*)d_in[9],  *b1 = (const float*)d_in[10];
    const float* g1 = (const float*)d_in[11], *be1 = (const float*)d_in[12];
    const float* m1 = (const float*)d_in[13], *v1 = (const float*)d_in[14];
    const float* W2 = (const float*)d_in[15], *b2 = (const float*)d_in[16];
    const float* g2 = (const float*)d_in[17], *be2 = (const float*)d_in[18];
    const float* m2 = (const float*)d_in[19], *v2 = (const float*)d_in[20];
    const float* Wm1 = (const float*)d_in[21], *bm1 = (const float*)d_in[22];
    const float* Wm2 = (const float*)d_in[23], *bm2 = (const float*)d_in[24];
    float* out = (float*)d_out;

    const int NB_NODE = (N_NODES + 255) / 256;
    const int NB_ELT  = (N_NODES * HID / 4 + 255) / 256;   // float4 elements
    const int NB_GEMM = (N_NODES + 63) / 64;
    const int NB_SCAT = (N_EDGES * 32 + 255) / 256;        // warp per edge

    // degrees -> dinv
    zero_deg_kernel<<<NB_NODE, 256>>>();
    deg_kernel<<<(N_EDGES + 255) / 256, 256>>>(dst);
    dinv_kernel<<<NB_NODE, 256>>>();

    // layer 0 (K=64, input = x)
    gemm_scale_kernel<64, false><<<NB_GEMM, 256>>>(x, W0);
    zero_agg_kernel<<<NB_ELT, 256>>>();
    scatter_kernel<<<NB_SCAT, 256>>>(src, dst);
    finalize_kernel<<<NB_ELT, 256>>>(b0, g0, be0, m0, v0);

    // layer 1 (K=128, input = g_act)
    gemm_scale_kernel<128, true><<<NB_GEMM, 256>>>(nullptr, W1);
    zero_agg_kernel<<<NB_ELT, 256>>>();
    scatter_kernel<<<NB_SCAT, 256>>>(src, dst);
    finalize_kernel<<<NB_ELT, 256>>>(b1, g1, be1, m1, v1);

    // layer 2
    gemm_scale_kernel<128, true><<<NB_GEMM, 256>>>(nullptr, W2);
    zero_agg_kernel<<<NB_ELT, 256>>>();
    scatter_kernel<<<NB_SCAT, 256>>>(src, dst);
    finalize_kernel<<<NB_ELT, 256>>>(b2, g2, be2, m2, v2);

    // MLP head
    mlp_kernel<<<NB_GEMM, 256>>>(Wm1, bm1, Wm2, bm2, out);
}

// round 2
// speedup vs baseline: 1.6471x; 1.6471x over previous
#include <cuda_runtime.h>

#define N_NODES 50000
#define N_EDGES 800000
#define HID 128
#define OUTD 64
#define BN_EPS 1e-5f

// ---------------- scratch (device globals: allocation-free) ----------------
__device__ int   g_cnt[N_NODES];
__device__ int   g_fill[N_NODES];
__device__ int   g_rowptr[N_NODES + 1];
__device__ int   g_colidx[N_EDGES];
__device__ float g_dinv[N_NODES];
__device__ __align__(16) float g_hp[(size_t)N_NODES * HID];   // (X@W)*dinv[row] / mlp hidden
__device__ __align__(16) float g_act[(size_t)N_NODES * HID];  // layer activations

// ---------------- CSR build ----------------
__global__ void zero_cnt_kernel() {
    int i = blockIdx.x * blockDim.x + threadIdx.x;
    if (i < N_NODES) { g_cnt[i] = 0; g_fill[i] = 0; }
}
__global__ void hist_kernel(const int* __restrict__ dst) {
    int e = blockIdx.x * blockDim.x + threadIdx.x;
    if (e < N_EDGES) atomicAdd(&g_cnt[dst[e]], 1);
}
// single-block inclusive scan -> exclusive rowptr; also emits dinv = rsqrt(1+deg)
__global__ void scan_dinv_kernel() {
    __shared__ int warp_sums[32];
    __shared__ int carry_sh;
    const int lane = threadIdx.x & 31, wid = threadIdx.x >> 5;
    if (threadIdx.x == 0) carry_sh = 0;
    __syncthreads();
    for (int base = 0; base < N_NODES; base += 1024) {
        int i = base + (int)threadIdx.x;
        int v = (i < N_NODES) ? g_cnt[i] : 0;
        if (i < N_NODES) g_dinv[i] = rsqrtf(1.0f + (float)v);
        int x = v;
#pragma unroll
        for (int o = 1; o < 32; o <<= 1) {
            int y = __shfl_up_sync(0xffffffffu, x, o);
            if (lane >= o) x += y;
        }
        if (lane == 31) warp_sums[wid] = x;
        __syncthreads();
        if (wid == 0) {
            int s = warp_sums[lane];
#pragma unroll
            for (int o = 1; o < 32; o <<= 1) {
                int y = __shfl_up_sync(0xffffffffu, s, o);
                if (lane >= o) s += y;
            }
            warp_sums[lane] = s;
        }
        __syncthreads();
        int incl = x + (wid > 0 ? warp_sums[wid - 1] : 0) + carry_sh;
        if (i < N_NODES) g_rowptr[i + 1] = incl;
        __syncthreads();
        if (threadIdx.x == 1023) carry_sh = incl;
        __syncthreads();
    }
    if (threadIdx.x == 0) g_rowptr[0] = 0;
}
__global__ void fill_csr_kernel(const int* __restrict__ src, const int* __restrict__ dst) {
    int e = blockIdx.x * blockDim.x + threadIdx.x;
    if (e < N_EDGES) {
        int d = dst[e];
        int p = g_rowptr[d] + atomicAdd(&g_fill[d], 1);
        g_colidx[p] = src[e];
    }
}

// ---------------- GEMM template: 128-row x NC-col tile, 8x(NC/16) per thread ----------
// SRCSEL: 0 = external X, 1 = g_act, 2 = g_hp
// EPI:    0 = scale by dinv[row] -> g_hp
//         1 = relu(acc + bias)   -> g_hp
//         2 = acc + bias         -> outext
template <int K, int NC, int SRCSEL, int EPI>
__global__ __launch_bounds__(256, 2) void gemm_kernel(const float* __restrict__ Xext,
                                                      const float* __restrict__ W,
                                                      const float* __restrict__ bias,
                                                      float* __restrict__ outext) {
    constexpr int KC = 16;
    constexpr int CPT = NC / 16;        // cols per thread: 8 or 4
    constexpr int NCH = K / KC;
    constexpr int BF4 = KC * NC / 4;    // float4s in B chunk
    constexpr int BPT = BF4 / 256;      // 2 (NC=128) or 1 (NC=64)

    __shared__ float As[KC][128];
    __shared__ float Bs[KC][NC];

    const float* __restrict__ X =
        (SRCSEL == 0) ? Xext : (SRCSEL == 1 ? (const float*)g_act : (const float*)g_hp);
    float* __restrict__ OUT = (EPI == 2) ? outext : (float*)g_hp;

    const int tid = threadIdx.x;
    const int row0 = blockIdx.x * 128;
    const int rowA = tid >> 1;
    const int kqA = (tid & 1) * 8;
    const bool aok = (row0 + rowA) < N_NODES;
    const float* Arow = X + (size_t)(row0 + rowA) * K;

    const int tx = tid & 15;
    const int ty = tid >> 4;

    float acc[8][CPT];
#pragma unroll
    for (int i = 0; i < 8; i++)
#pragma unroll
        for (int j = 0; j < CPT; j++) acc[i][j] = 0.f;

    float4 pa0, pa1;
    float4 pb[BPT];
    const float4 z4 = make_float4(0.f, 0.f, 0.f, 0.f);

    // prefetch chunk 0
    {
        pa0 = aok ? *reinterpret_cast<const float4*>(Arow + kqA) : z4;
        pa1 = aok ? *reinterpret_cast<const float4*>(Arow + kqA + 4) : z4;
#pragma unroll
        for (int t = 0; t < BPT; t++) {
            int j = tid + t * 256;
            int kb = j / (NC / 4), cb = j % (NC / 4);
            pb[t] = *reinterpret_cast<const float4*>(W + (size_t)kb * NC + cb * 4);
        }
    }
    // store chunk 0
    As[kqA + 0][rowA] = pa0.x; As[kqA + 1][rowA] = pa0.y;
    As[kqA + 2][rowA] = pa0.z; As[kqA + 3][rowA] = pa0.w;
    As[kqA + 4][rowA] = pa1.x; As[kqA + 5][rowA] = pa1.y;
    As[kqA + 6][rowA] = pa1.z; As[kqA + 7][rowA] = pa1.w;
#pragma unroll
    for (int t = 0; t < BPT; t++)
        reinterpret_cast<float4*>(&Bs[0][0])[tid + t * 256] = pb[t];
    __syncthreads();

    for (int c = 0; c < NCH; c++) {
        if (c + 1 < NCH) {
            int kc = (c + 1) * KC;
            pa0 = aok ? *reinterpret_cast<const float4*>(Arow + kc + kqA) : z4;
            pa1 = aok ? *reinterpret_cast<const float4*>(Arow + kc + kqA + 4) : z4;
#pragma unroll
            for (int t = 0; t < BPT; t++) {
                int j = tid + t * 256;
                int kb = j / (NC / 4), cb = j % (NC / 4);
                pb[t] = *reinterpret_cast<const float4*>(W + (size_t)(kc + kb) * NC + cb * 4);
            }
        }
#pragma unroll
        for (int k = 0; k < KC; ++k) {
            float4 a0 = *reinterpret_cast<const float4*>(&As[k][ty * 8]);
            float4 a1 = *reinterpret_cast<const float4*>(&As[k][ty * 8 + 4]);
            float a[8] = {a0.x, a0.y, a0.z, a0.w, a1.x, a1.y, a1.z, a1.w};
            float b[CPT];
            if (CPT == 8) {
                float4 b0 = *reinterpret_cast<const float4*>(&Bs[k][tx * 8]);
                float4 b1 = *reinterpret_cast<const float4*>(&Bs[k][tx * 8 + 4]);
                b[0] = b0.x; b[1] = b0.y; b[2] = b0.z; b[3] = b0.w;
                b[4] = b1.x; b[5] = b1.y; b[6] = b1.z; b[7] = b1.w;
            } else {
                float4 b0 = *reinterpret_cast<const float4*>(&Bs[k][tx * 4]);
                b[0] = b0.x; b[1] = b0.y; b[2] = b0.z; b[3] = b0.w;
            }
#pragma unroll
            for (int i = 0; i < 8; i++)
#pragma unroll
                for (int j = 0; j < CPT; j++) acc[i][j] = fmaf(a[i], b[j], acc[i][j]);
        }
        __syncthreads();
        if (c + 1 < NCH) {
            As[kqA + 0][rowA] = pa0.x; As[kqA + 1][rowA] = pa0.y;
            As[kqA + 2][rowA] = pa0.z; As[kqA + 3][rowA] = pa0.w;
            As[kqA + 4][rowA] = pa1.x; As[kqA + 5][rowA] = pa1.y;
            As[kqA + 6][rowA] = pa1.z; As[kqA + 7][rowA] = pa1.w;
#pragma unroll
            for (int t = 0; t < BPT; t++)
                reinterpret_cast<float4*>(&Bs[0][0])[tid + t * 256] = pb[t];
            __syncthreads();
        }
    }

    // epilogue
    if (EPI == 0) {
#pragma unroll
        for (int i = 0; i < 8; i++) {
            int r = row0 + ty * 8 + i;
            if (r < N_NODES) {
                float d = g_dinv[r];
                float4 o0 = make_float4(acc[i][0] * d, acc[i][1] * d, acc[i][2] * d, acc[i][3] * d);
                float4 o1 = make_float4(acc[i][4] * d, acc[i][5] * d, acc[i][6] * d, acc[i][7] * d);
                float4* p = reinterpret_cast<float4*>(g_hp + (size_t)r * HID + tx * 8);
                p[0] = o0; p[1] = o1;
            }
        }
    } else if (EPI == 1) {
        float4 b0 = reinterpret_cast<const float4*>(bias)[tx * 2];
        float4 b1 = reinterpret_cast<const float4*>(bias)[tx * 2 + 1];
#pragma unroll
        for (int i = 0; i < 8; i++) {
            int r = row0 + ty * 8 + i;
            if (r < N_NODES) {
                float4 o0 = make_float4(fmaxf(acc[i][0] + b0.x, 0.f), fmaxf(acc[i][1] + b0.y, 0.f),
                                        fmaxf(acc[i][2] + b0.z, 0.f), fmaxf(acc[i][3] + b0.w, 0.f));
                float4 o1 = make_float4(fmaxf(acc[i][4] + b1.x, 0.f), fmaxf(acc[i][5] + b1.y, 0.f),
                                        fmaxf(acc[i][6] + b1.z, 0.f), fmaxf(acc[i][7] + b1.w, 0.f));
                float4* p = reinterpret_cast<float4*>(OUT + (size_t)r * HID + tx * 8);
                p[0] = o0; p[1] = o1;
            }
        }
    } else {
        float4 b0 = reinterpret_cast<const float4*>(bias)[tx];
#pragma unroll
        for (int i = 0; i < 8; i++) {
            int r = row0 + ty * 8 + i;
            if (r < N_NODES) {
                float4 o = make_float4(acc[i][0] + b0.x, acc[i][1] + b0.y,
                                       acc[i][2] + b0.z, acc[i][3] + b0.w);
                *reinterpret_cast<float4*>(OUT + (size_t)r * OUTD + tx * 4) = o;
            }
        }
    }
}

// ---------------- CSR aggregation + BN + ReLU fused (warp per dst node) -----------
__global__ __launch_bounds__(256) void agg_bn_kernel(const float* __restrict__ bias,
                                                     const float* __restrict__ gam,
                                                     const float* __restrict__ bet,
                                                     const float* __restrict__ mu,
                                                     const float* __restrict__ var) {
    int n = (blockIdx.x * 256 + threadIdx.x) >> 5;
    int lane = threadIdx.x & 31;
    if (n >= N_NODES) return;

    // self term: hp[n] (already scaled by dinv[n])
    float4 acc = reinterpret_cast<const float4*>(g_hp + (size_t)n * HID)[lane];

    int e = g_rowptr[n];
    const int e1 = g_rowptr[n + 1];
    for (; e + 4 <= e1; e += 4) {
        int s0 = g_colidx[e], s1 = g_colidx[e + 1], s2 = g_colidx[e + 2], s3 = g_colidx[e + 3];
        float4 a0 = reinterpret_cast<const float4*>(g_hp + (size_t)s0 * HID)[lane];
        float4 a1 = reinterpret_cast<const float4*>(g_hp + (size_t)s1 * HID)[lane];
        float4 a2 = reinterpret_cast<const float4*>(g_hp + (size_t)s2 * HID)[lane];
        float4 a3 = reinterpret_cast<const float4*>(g_hp + (size_t)s3 * HID)[lane];
        acc.x += (a0.x + a1.x) + (a2.x + a3.x);
        acc.y += (a0.y + a1.y) + (a2.y + a3.y);
        acc.z += (a0.z + a1.z) + (a2.z + a3.z);
        acc.w += (a0.w + a1.w) + (a2.w + a3.w);
    }
    for (; e < e1; e++) {
        int s = g_colidx[e];
        float4 a = reinterpret_cast<const float4*>(g_hp + (size_t)s * HID)[lane];
        acc.x += a.x; acc.y += a.y; acc.z += a.z; acc.w += a.w;
    }

    const float d = g_dinv[n];
    float4 gg = reinterpret_cast<const float4*>(gam)[lane];
    float4 vv = reinterpret_cast<const float4*>(var)[lane];
    float4 mm = reinterpret_cast<const float4*>(mu)[lane];
    float4 be = reinterpret_cast<const float4*>(bet)[lane];
    float4 bb = reinterpret_cast<const float4*>(bias)[lane];
    float4 o;
    {
        float s;
        s = gg.x * rsqrtf(vv.x + BN_EPS); o.x = fmaxf((d * acc.x + bb.x - mm.x) * s + be.x, 0.f);
        s = gg.y * rsqrtf(vv.y + BN_EPS); o.y = fmaxf((d * acc.y + bb.y - mm.y) * s + be.y, 0.f);
        s = gg.z * rsqrtf(vv.z + BN_EPS); o.z = fmaxf((d * acc.z + bb.z - mm.z) * s + be.z, 0.f);
        s = gg.w * rsqrtf(vv.w + BN_EPS); o.w = fmaxf((d * acc.w + bb.w - mm.w) * s + be.w, 0.f);
    }
    reinterpret_cast<float4*>(g_act + (size_t)n * HID)[lane] = o;
}

// ---------------- launch ----------------
extern "C" void kernel_launch(void* const* d_in, const int* in_sizes, int n_in,
                              void* d_out, int out_size) {
    (void)in_sizes; (void)n_in; (void)out_size;
    const float* x   = (const float*)d_in[0];
    const int*   src = (const int*)d_in[1];
    const int*   dst = (const int*)d_in[2];
    const float* W0 = (const float*)d_in[3],  *b0 = (const float*)d_in[4];
    const float* g0 = (const float*)d_in[5],  *be0 = (const float*)d_in[6];
    const float* m0 = (const float*)d_in[7],  *v0 = (const float*)d_in[8];
    const float* W1 = (const float*)d_in[9],  *b1 = (const float*)d_in[10];
    const float* g1 = (const float*)d_in[11], *be1 = (const float*)d_in[12];
    const float* m1 = (const float*)d_in[13], *v1 = (const float*)d_in[14];
    const float* W2 = (const float*)d_in[15], *b2 = (const float*)d_in[16];
    const float* g2 = (const float*)d_in[17], *be2 = (const float*)d_in[18];
    const float* m2 = (const float*)d_in[19], *v2 = (const float*)d_in[20];
    const float* Wm1 = (const float*)d_in[21], *bm1 = (const float*)d_in[22];
    const float* Wm2 = (const float*)d_in[23], *bm2 = (const float*)d_in[24];
    float* out = (float*)d_out;

    const int NB_NODE = (N_NODES + 255) / 256;
    const int NB_EDGE = (N_EDGES + 255) / 256;
    const int NB_GEMM = (N_NODES + 127) / 128;
    const int NB_AGG  = (N_NODES + 7) / 8;     // warp per node, 8 warps/block

    // CSR + dinv (rebuilt every call; deterministic work)
    zero_cnt_kernel<<<NB_NODE, 256>>>();
    hist_kernel<<<NB_EDGE, 256>>>(dst);
    scan_dinv_kernel<<<1, 1024>>>();
    fill_csr_kernel<<<NB_EDGE, 256>>>(src, dst);

    // layer 0
    gemm_kernel<64, 128, 0, 0><<<NB_GEMM, 256>>>(x, W0, nullptr, nullptr);
    agg_bn_kernel<<<NB_AGG, 256>>>(b0, g0, be0, m0, v0);
    // layer 1
    gemm_kernel<128, 128, 1, 0><<<NB_GEMM, 256>>>(nullptr, W1, nullptr, nullptr);
    agg_bn_kernel<<<NB_AGG, 256>>>(b1, g1, be1, m1, v1);
    // layer 2
    gemm_kernel<128, 128, 1, 0><<<NB_GEMM, 256>>>(nullptr, W2, nullptr, nullptr);
    agg_bn_kernel<<<NB_AGG, 256>>>(b2, g2, be2, m2, v2);

    // MLP head
    gemm_kernel<128, 128, 1, 1><<<NB_GEMM, 256>>>(nullptr, Wm1, bm1, nullptr);  // -> g_hp
    gemm_kernel<128, 64, 2, 2><<<NB_GEMM, 256>>>(nullptr, Wm2, bm2, out);
}

// round 4
// speedup vs baseline: 2.4507x; 1.4879x over previous
#include <cuda_runtime.h>
#include <cuda_bf16.h>
#include <cstdint>

#define N_NODES 50000
#define N_EDGES 800000
#define HID 128
#define OUTD 64
#define BN_EPS 1e-5f

// ---------------- scratch (device globals: allocation-free) ----------------
__device__ int   g_cnt[N_NODES];
__device__ int   g_fill[N_NODES];
__device__ int   g_rowptr[N_NODES + 1];
__device__ int   g_colidx[N_EDGES];
__device__ float g_dinv[N_NODES];
__device__ __align__(16) float g_hp[(size_t)N_NODES * HID];   // (X@W)*dinv[row] / mlp hidden
__device__ __align__(16) float g_act[(size_t)N_NODES * HID];  // layer activations

// ---------------- CSR build ----------------
__global__ void zero_cnt_kernel() {
    int i = blockIdx.x * blockDim.x + threadIdx.x;
    if (i < N_NODES) { g_cnt[i] = 0; g_fill[i] = 0; }
}
__global__ void hist_kernel(const int* __restrict__ dst) {
    int e = blockIdx.x * blockDim.x + threadIdx.x;
    if (e < N_EDGES) atomicAdd(&g_cnt[dst[e]], 1);
}
__global__ void scan_dinv_kernel() {
    __shared__ int warp_sums[32];
    __shared__ int carry_sh;
    const int lane = threadIdx.x & 31, wid = threadIdx.x >> 5;
    if (threadIdx.x == 0) carry_sh = 0;
    __syncthreads();
    for (int base = 0; base < N_NODES; base += 1024) {
        int i = base + (int)threadIdx.x;
        int v = (i < N_NODES) ? g_cnt[i] : 0;
        if (i < N_NODES) g_dinv[i] = rsqrtf(1.0f + (float)v);
        int x = v;
#pragma unroll
        for (int o = 1; o < 32; o <<= 1) {
            int y = __shfl_up_sync(0xffffffffu, x, o);
            if (lane >= o) x += y;
        }
        if (lane == 31) warp_sums[wid] = x;
        __syncthreads();
        if (wid == 0) {
            int s = warp_sums[lane];
#pragma unroll
            for (int o = 1; o < 32; o <<= 1) {
                int y = __shfl_up_sync(0xffffffffu, s, o);
                if (lane >= o) s += y;
            }
            warp_sums[lane] = s;
        }
        __syncthreads();
        int incl = x + (wid > 0 ? warp_sums[wid - 1] : 0) + carry_sh;
        if (i < N_NODES) g_rowptr[i + 1] = incl;
        __syncthreads();
        if (threadIdx.x == 1023) carry_sh = incl;
        __syncthreads();
    }
    if (threadIdx.x == 0) g_rowptr[0] = 0;
}
__global__ void fill_csr_kernel(const int* __restrict__ src, const int* __restrict__ dst) {
    int e = blockIdx.x * blockDim.x + threadIdx.x;
    if (e < N_EDGES) {
        int d = dst[e];
        int p = g_rowptr[d] + atomicAdd(&g_fill[d], 1);
        g_colidx[p] = src[e];
    }
}

// ---------------- helpers ----------------
__device__ __forceinline__ void mma16816(float* d, const uint32_t* a, const uint32_t* b) {
    asm volatile(
        "mma.sync.aligned.m16n8k16.row.col.f32.bf16.bf16.f32 "
        "{%0,%1,%2,%3}, {%4,%5,%6,%7}, {%8,%9}, {%0,%1,%2,%3};"
        : "+f"(d[0]), "+f"(d[1]), "+f"(d[2]), "+f"(d[3])
        : "r"(a[0]), "r"(a[1]), "r"(a[2]), "r"(a[3]), "r"(b[0]), "r"(b[1]));
}
__device__ __forceinline__ uint32_t pack_bf16x2(__nv_bfloat16 a, __nv_bfloat16 b) {
    return (uint32_t)__bfloat16_as_ushort(a) | ((uint32_t)__bfloat16_as_ushort(b) << 16);
}
__device__ __forceinline__ void split2(float v, __nv_bfloat16& h, __nv_bfloat16& l) {
    h = __float2bfloat16_rn(v);
    l = __float2bfloat16_rn(v - __bfloat162float(h));
}

// ---------------- HMMA GEMM: D[128 x NC] = X[128 x K] @ W[K x NC] ---------------
// bf16 hi/lo split: D = hi*hi + hi*lo + lo*hi accumulated in fp32.
// SRCSEL: 0 = external X, 1 = g_act, 2 = g_hp
// EPI: 0 = acc*dinv[row] -> g_hp ; 1 = relu(acc+bias) -> g_hp ; 2 = acc+bias -> outext
template <int K, int NC, int SRCSEL, int EPI>
__global__ __launch_bounds__(256) void mma_gemm_kernel(const float* __restrict__ Xext,
                                                       const float* __restrict__ W,
                                                       const float* __restrict__ bias,
                                                       float* __restrict__ outext) {
    constexpr int LDA = 72;            // bf16 stride (conflict-free for frag loads)
    constexpr int NPW = NC / 16;       // 8-wide n-frags per warp (warp tile N = NC/2)
    extern __shared__ __align__(16) char smem[];
    __nv_bfloat16* As_hi = (__nv_bfloat16*)smem;          // [128][LDA]
    __nv_bfloat16* As_lo = As_hi + 128 * LDA;
    __nv_bfloat16* Bs_hi = As_lo + 128 * LDA;             // [NC][LDA] (k-contig = col-major B)
    __nv_bfloat16* Bs_lo = Bs_hi + NC * LDA;

    const int tid = threadIdx.x, wid = tid >> 5, lane = tid & 31;
    const int row0 = blockIdx.x * 128;
    const float* __restrict__ X =
        (SRCSEL == 0) ? Xext : (SRCSEL == 1 ? (const float*)g_act : (const float*)g_hp);

    const int m0 = (wid >> 1) * 32;
    const int n0 = (wid & 1) * (NC / 2);
    const int gid = lane >> 2, tid4 = lane & 3;

    float acc[2][NPW][4];
#pragma unroll
    for (int mi = 0; mi < 2; mi++)
#pragma unroll
        for (int ni = 0; ni < NPW; ni++)
#pragma unroll
            for (int j = 0; j < 4; j++) acc[mi][ni][j] = 0.f;

    for (int kc = 0; kc < K; kc += 64) {
        if (kc) __syncthreads();
        // fill A chunk: rows of X, fp32 -> bf16 hi/lo
#pragma unroll
        for (int it = 0; it < 8; it++) {
            int i = tid + it * 256;               // i < 2048
            int r = i >> 4, q = (i & 15) * 4;
            float4 v = make_float4(0.f, 0.f, 0.f, 0.f);
            if (row0 + r < N_NODES)
                v = *reinterpret_cast<const float4*>(X + (size_t)(row0 + r) * K + kc + q);
            __nv_bfloat16 h0, h1, h2, h3, l0, l1, l2, l3;
            split2(v.x, h0, l0); split2(v.y, h1, l1);
            split2(v.z, h2, l2); split2(v.w, h3, l3);
            *reinterpret_cast<uint2*>(As_hi + r * LDA + q) =
                make_uint2(pack_bf16x2(h0, h1), pack_bf16x2(h2, h3));
            *reinterpret_cast<uint2*>(As_lo + r * LDA + q) =
                make_uint2(pack_bf16x2(l0, l1), pack_bf16x2(l2, l3));
        }
        // fill B chunk transposed: Bs[n][k] = W[kc+k][n]
#pragma unroll
        for (int it = 0; it < NC / 16; it++) {
            int i = tid + it * 256;               // i < NC*16
            int n = i % NC, q = (i / NC) * 4;
            float w0 = W[(size_t)(kc + q + 0) * NC + n];
            float w1 = W[(size_t)(kc + q + 1) * NC + n];
            float w2 = W[(size_t)(kc + q + 2) * NC + n];
            float w3 = W[(size_t)(kc + q + 3) * NC + n];
            __nv_bfloat16 h0, h1, h2, h3, l0, l1, l2, l3;
            split2(w0, h0, l0); split2(w1, h1, l1);
            split2(w2, h2, l2); split2(w3, h3, l3);
            *reinterpret_cast<uint2*>(Bs_hi + n * LDA + q) =
                make_uint2(pack_bf16x2(h0, h1), pack_bf16x2(h2, h3));
            *reinterpret_cast<uint2*>(Bs_lo + n * LDA + q) =
                make_uint2(pack_bf16x2(l0, l1), pack_bf16x2(l2, l3));
        }
        __syncthreads();

#pragma unroll
        for (int k16 = 0; k16 < 64; k16 += 16) {
            uint32_t bh[NPW][2], bl[NPW][2];
#pragma unroll
            for (int ni = 0; ni < NPW; ni++) {
                const __nv_bfloat16* bp = Bs_hi + (n0 + ni * 8 + gid) * LDA + k16 + tid4 * 2;
                const __nv_bfloat16* bq = Bs_lo + (n0 + ni * 8 + gid) * LDA + k16 + tid4 * 2;
                bh[ni][0] = *reinterpret_cast<const uint32_t*>(bp);
                bh[ni][1] = *reinterpret_cast<const uint32_t*>(bp + 8);
                bl[ni][0] = *reinterpret_cast<const uint32_t*>(bq);
                bl[ni][1] = *reinterpret_cast<const uint32_t*>(bq + 8);
            }
#pragma unroll
            for (int mi = 0; mi < 2; mi++) {
                const int r = m0 + mi * 16 + gid;
                const int c = k16 + tid4 * 2;
                uint32_t ah[4], al[4];
                ah[0] = *reinterpret_cast<const uint32_t*>(As_hi + r * LDA + c);
                ah[1] = *reinterpret_cast<const uint32_t*>(As_hi + (r + 8) * LDA + c);
                ah[2] = *reinterpret_cast<const uint32_t*>(As_hi + r * LDA + c + 8);
                ah[3] = *reinterpret_cast<const uint32_t*>(As_hi + (r + 8) * LDA + c + 8);
                al[0] = *reinterpret_cast<const uint32_t*>(As_lo + r * LDA + c);
                al[1] = *reinterpret_cast<const uint32_t*>(As_lo + (r + 8) * LDA + c);
                al[2] = *reinterpret_cast<const uint32_t*>(As_lo + r * LDA + c + 8);
                al[3] = *reinterpret_cast<const uint32_t*>(As_lo + (r + 8) * LDA + c + 8);
#pragma unroll
                for (int ni = 0; ni < NPW; ni++) {
                    mma16816(acc[mi][ni], ah, bh[ni]);
                    mma16816(acc[mi][ni], ah, bl[ni]);
                    mma16816(acc[mi][ni], al, bh[ni]);
                }
            }
        }
    }

    // ---- epilogue from register accumulators ----
#pragma unroll
    for (int mi = 0; mi < 2; mi++) {
#pragma unroll
        for (int rr = 0; rr < 2; rr++) {
            int r = row0 + m0 + mi * 16 + gid + rr * 8;
            if (r < N_NODES) {
                float d = (EPI == 0) ? g_dinv[r] : 0.f;
                float* orow =
                    (EPI == 2) ? (outext + (size_t)r * OUTD) : ((float*)g_hp + (size_t)r * HID);
#pragma unroll
                for (int ni = 0; ni < NPW; ni++) {
                    int cn = n0 + ni * 8 + tid4 * 2;
                    float c0 = acc[mi][ni][rr * 2 + 0];
                    float c1 = acc[mi][ni][rr * 2 + 1];
                    float2 o;
                    if (EPI == 0) {
                        o.x = c0 * d; o.y = c1 * d;
                    } else {
                        float2 bb = *reinterpret_cast<const float2*>(bias + cn);
                        if (EPI == 1) {
                            o.x = fmaxf(c0 + bb.x, 0.f);
                            o.y = fmaxf(c1 + bb.y, 0.f);
                        } else {
                            o.x = c0 + bb.x; o.y = c1 + bb.y;
                        }
                    }
                    *reinterpret_cast<float2*>(orow + cn) = o;
                }
            }
        }
    }
}

// ---------------- CSR aggregation + BN + ReLU fused (warp per dst node) -----------
__global__ __launch_bounds__(256) void agg_bn_kernel(const float* __restrict__ bias,
                                                     const float* __restrict__ gam,
                                                     const float* __restrict__ bet,
                                                     const float* __restrict__ mu,
                                                     const float* __restrict__ var) {
    int n = (blockIdx.x * 256 + threadIdx.x) >> 5;
    int lane = threadIdx.x & 31;
    if (n >= N_NODES) return;

    float4 acc = reinterpret_cast<const float4*>(g_hp + (size_t)n * HID)[lane];

    int e = g_rowptr[n];
    const int e1 = g_rowptr[n + 1];
    for (; e + 4 <= e1; e += 4) {
        int s0 = g_colidx[e], s1 = g_colidx[e + 1], s2 = g_colidx[e + 2], s3 = g_colidx[e + 3];
        float4 a0 = reinterpret_cast<const float4*>(g_hp + (size_t)s0 * HID)[lane];
        float4 a1 = reinterpret_cast<const float4*>(g_hp + (size_t)s1 * HID)[lane];
        float4 a2 = reinterpret_cast<const float4*>(g_hp + (size_t)s2 * HID)[lane];
        float4 a3 = reinterpret_cast<const float4*>(g_hp + (size_t)s3 * HID)[lane];
        acc.x += (a0.x + a1.x) + (a2.x + a3.x);
        acc.y += (a0.y + a1.y) + (a2.y + a3.y);
        acc.z += (a0.z + a1.z) + (a2.z + a3.z);
        acc.w += (a0.w + a1.w) + (a2.w + a3.w);
    }
    for (; e < e1; e++) {
        int s = g_colidx[e];
        float4 a = reinterpret_cast<const float4*>(g_hp + (size_t)s * HID)[lane];
        acc.x += a.x; acc.y += a.y; acc.z += a.z; acc.w += a.w;
    }

    const float d = g_dinv[n];
    float4 gg = reinterpret_cast<const float4*>(gam)[lane];
    float4 vv = reinterpret_cast<const float4*>(var)[lane];
    float4 mm = reinterpret_cast<const float4*>(mu)[lane];
    float4 be = reinterpret_cast<const float4*>(bet)[lane];
    float4 bb = reinterpret_cast<const float4*>(bias)[lane];
    float4 o;
    {
        float s;
        s = gg.x * rsqrtf(vv.x + BN_EPS); o.x = fmaxf((d * acc.x + bb.x - mm.x) * s + be.x, 0.f);
        s = gg.y * rsqrtf(vv.y + BN_EPS); o.y = fmaxf((d * acc.y + bb.y - mm.y) * s + be.y, 0.f);
        s = gg.z * rsqrtf(vv.z + BN_EPS); o.z = fmaxf((d * acc.z + bb.z - mm.z) * s + be.z, 0.f);
        s = gg.w * rsqrtf(vv.w + BN_EPS); o.w = fmaxf((d * acc.w + bb.w - mm.w) * s + be.w, 0.f);
    }
    reinterpret_cast<float4*>(g_act + (size_t)n * HID)[lane] = o;
}

// ---------------- launch ----------------
extern "C" void kernel_launch(void* const* d_in, const int* in_sizes, int n_in,
                              void* d_out, int out_size) {
    (void)in_sizes; (void)n_in; (void)out_size;
    const float* x   = (const float*)d_in[0];
    const int*   src = (const int*)d_in[1];
    const int*   dst = (const int*)d_in[2];
    const float* W0 = (const float*)d_in[3],  *b0 = (const float*)d_in[4];
    const float* g0 = (const float*)d_in[5],  *be0 = (const float*)d_in[6];
    const float* m0 = (const float*)d_in[7],  *v0 = (const float*)d_in[8];
    const float* W1 = (const float*)d_in[9],  *b1 = (const float*)d_in[10];
    const float* g1 = (const float*)d_in[11], *be1 = (const float*)d_in[12];
    const float* m1 = (const float*)d_in[13], *v1 = (const float*)d_in[14];
    const float* W2 = (const float*)d_in[15], *b2 = (const float*)d_in[16];
    const float* g2 = (const float*)d_in[17], *be2 = (const float*)d_in[18];
    const float* m2 = (const float*)d_in[19], *v2 = (const float*)d_in[20];
    const float* Wm1 = (const float*)d_in[21], *bm1 = (const float*)d_in[22];
    const float* Wm2 = (const float*)d_in[23], *bm2 = (const float*)d_in[24];
    float* out = (float*)d_out;

    const int NB_NODE = (N_NODES + 255) / 256;
    const int NB_EDGE = (N_EDGES + 255) / 256;
    const int NB_GEMM = (N_NODES + 127) / 128;
    const int NB_AGG  = (N_NODES + 7) / 8;

    // dynamic smem: (2*128 + 2*NC) * 72 * 2 bytes
    constexpr int SM_128 = (2 * 128 + 2 * 128) * 72 * 2;  // 73728
    constexpr int SM_64  = (2 * 128 + 2 * 64) * 72 * 2;   // 55296

    cudaFuncSetAttribute(mma_gemm_kernel<64, 128, 0, 0>,
                         cudaFuncAttributeMaxDynamicSharedMemorySize, SM_128);
    cudaFuncSetAttribute(mma_gemm_kernel<128, 128, 1, 0>,
                         cudaFuncAttributeMaxDynamicSharedMemorySize, SM_128);
    cudaFuncSetAttribute(mma_gemm_kernel<128, 128, 1, 1>,
                         cudaFuncAttributeMaxDynamicSharedMemorySize, SM_128);
    cudaFuncSetAttribute(mma_gemm_kernel<128, 64, 2, 2>,
                         cudaFuncAttributeMaxDynamicSharedMemorySize, SM_64);

    // CSR + dinv
    zero_cnt_kernel<<<NB_NODE, 256>>>();
    hist_kernel<<<NB_EDGE, 256>>>(dst);
    scan_dinv_kernel<<<1, 1024>>>();
    fill_csr_kernel<<<NB_EDGE, 256>>>(src, dst);

    // layer 0
    mma_gemm_kernel<64, 128, 0, 0><<<NB_GEMM, 256, SM_128>>>(x, W0, nullptr, nullptr);
    agg_bn_kernel<<<NB_AGG, 256>>>(b0, g0, be0, m0, v0);
    // layer 1
    mma_gemm_kernel<128, 128, 1, 0><<<NB_GEMM, 256, SM_128>>>(nullptr, W1, nullptr, nullptr);
    agg_bn_kernel<<<NB_AGG, 256>>>(b1, g1, be1, m1, v1);
    // layer 2
    mma_gemm_kernel<128, 128, 1, 0><<<NB_GEMM, 256, SM_128>>>(nullptr, W2, nullptr, nullptr);
    agg_bn_kernel<<<NB_AGG, 256>>>(b2, g2, be2, m2, v2);

    // MLP head
    mma_gemm_kernel<128, 128, 1, 1><<<NB_GEMM, 256, SM_128>>>(nullptr, Wm1, bm1, nullptr);
    mma_gemm_kernel<128, 64, 2, 2><<<NB_GEMM, 256, SM_64>>>(nullptr, Wm2, bm2, out);
}

// round 5
// speedup vs baseline: 2.4733x; 1.0092x over previous
#include <cuda_runtime.h>
#include <cuda_bf16.h>
#include <cuda_fp16.h>
#include <cstdint>

#define N_NODES 50000
#define N_EDGES 800000
#define HID 128
#define OUTD 64
#define BN_EPS 1e-5f

// ---------------- scratch (device globals: allocation-free) ----------------
__device__ int   g_cnt[N_NODES];
__device__ int   g_rank[N_EDGES];
__device__ int   g_rowptr[N_NODES + 1];
__device__ int   g_colidx[N_EDGES];
__device__ float g_dinv[N_NODES];
__device__ __align__(16) __half g_hp16[(size_t)N_NODES * HID];  // (X@W)*dinv[row], fp16
__device__ __align__(16) float g_hp[(size_t)N_NODES * HID];     // MLP hidden (fp32)
__device__ __align__(16) float g_act[(size_t)N_NODES * HID];    // layer activations

// ---------------- CSR build ----------------
__global__ void zero_cnt_kernel() {
    int i = blockIdx.x * blockDim.x + threadIdx.x;
    if (i < N_NODES) g_cnt[i] = 0;
}
__global__ void hist_kernel(const int* __restrict__ dst) {
    int e = blockIdx.x * blockDim.x + threadIdx.x;
    if (e < N_EDGES) g_rank[e] = atomicAdd(&g_cnt[dst[e]], 1);
}
// single-block scan, 8 elements/thread (7 iterations over 50000)
__global__ void scan_dinv_kernel() {
    __shared__ int warp_sums[32];
    __shared__ int carry_sh;
    const int lane = threadIdx.x & 31, wid = threadIdx.x >> 5;
    if (threadIdx.x == 0) carry_sh = 0;
    __syncthreads();
    for (int base = 0; base < N_NODES; base += 8192) {
        const int c = carry_sh;
        const int idx0 = base + (int)threadIdx.x * 8;
        int v[8];
        if (idx0 + 8 <= N_NODES) {
            int4 a = *reinterpret_cast<const int4*>(g_cnt + idx0);
            int4 b = *reinterpret_cast<const int4*>(g_cnt + idx0 + 4);
            v[0] = a.x; v[1] = a.y; v[2] = a.z; v[3] = a.w;
            v[4] = b.x; v[5] = b.y; v[6] = b.z; v[7] = b.w;
        } else {
#pragma unroll
            for (int j = 0; j < 8; j++) v[j] = (idx0 + j < N_NODES) ? g_cnt[idx0 + j] : 0;
        }
        int p[8];
        p[0] = v[0];
#pragma unroll
        for (int j = 1; j < 8; j++) p[j] = p[j - 1] + v[j];
#pragma unroll
        for (int j = 0; j < 8; j++)
            if (idx0 + j < N_NODES) g_dinv[idx0 + j] = rsqrtf(1.0f + (float)v[j]);
        const int tot = p[7];
        int x = tot;
#pragma unroll
        for (int o = 1; o < 32; o <<= 1) {
            int y = __shfl_up_sync(0xffffffffu, x, o);
            if (lane >= o) x += y;
        }
        if (lane == 31) warp_sums[wid] = x;
        __syncthreads();
        if (wid == 0) {
            int s = warp_sums[lane];
#pragma unroll
            for (int o = 1; o < 32; o <<= 1) {
                int y = __shfl_up_sync(0xffffffffu, s, o);
                if (lane >= o) s += y;
            }
            warp_sums[lane] = s;
        }
        __syncthreads();
        const int basep = c + (wid > 0 ? warp_sums[wid - 1] : 0) + (x - tot);
#pragma unroll
        for (int j = 0; j < 8; j++)
            if (idx0 + j < N_NODES) g_rowptr[idx0 + j + 1] = basep + p[j];
        __syncthreads();
        if (threadIdx.x == 0) carry_sh = c + warp_sums[31];
        __syncthreads();
    }
    if (threadIdx.x == 0) g_rowptr[0] = 0;
}
// atomic-free fill using precomputed ranks
__global__ void fill_csr_kernel(const int* __restrict__ src, const int* __restrict__ dst) {
    int e = blockIdx.x * blockDim.x + threadIdx.x;
    if (e < N_EDGES) g_colidx[g_rowptr[dst[e]] + g_rank[e]] = src[e];
}

// ---------------- helpers ----------------
__device__ __forceinline__ void mma16816(float* d, const uint32_t* a, const uint32_t* b) {
    asm volatile(
        "mma.sync.aligned.m16n8k16.row.col.f32.bf16.bf16.f32 "
        "{%0,%1,%2,%3}, {%4,%5,%6,%7}, {%8,%9}, {%0,%1,%2,%3};"
        : "+f"(d[0]), "+f"(d[1]), "+f"(d[2]), "+f"(d[3])
        : "r"(a[0]), "r"(a[1]), "r"(a[2]), "r"(a[3]), "r"(b[0]), "r"(b[1]));
}
__device__ __forceinline__ uint32_t pack_bf16x2(__nv_bfloat16 a, __nv_bfloat16 b) {
    return (uint32_t)__bfloat16_as_ushort(a) | ((uint32_t)__bfloat16_as_ushort(b) << 16);
}
__device__ __forceinline__ void split2(float v, __nv_bfloat16& h, __nv_bfloat16& l) {
    h = __float2bfloat16_rn(v);
    l = __float2bfloat16_rn(v - __bfloat162float(h));
}

// ---------------- HMMA GEMM: D[128 x NC] = X[128 x K] @ W[K x NC] ---------------
// bf16 hi/lo split: D = hi*hi + hi*lo + lo*hi accumulated in fp32.
// SRCSEL: 0 = external X, 1 = g_act, 2 = g_hp
// EPI: 0 = acc*dinv[row] -> g_hp16 (fp16!)
//      1 = relu(acc+bias) -> g_hp (fp32)
//      2 = acc+bias -> outext
template <int K, int NC, int SRCSEL, int EPI>
__global__ __launch_bounds__(256) void mma_gemm_kernel(const float* __restrict__ Xext,
                                                       const float* __restrict__ W,
                                                       const float* __restrict__ bias,
                                                       float* __restrict__ outext) {
    constexpr int LDA = 72;
    constexpr int NPW = NC / 16;
    extern __shared__ __align__(16) char smem[];
    __nv_bfloat16* As_hi = (__nv_bfloat16*)smem;
    __nv_bfloat16* As_lo = As_hi + 128 * LDA;
    __nv_bfloat16* Bs_hi = As_lo + 128 * LDA;
    __nv_bfloat16* Bs_lo = Bs_hi + NC * LDA;

    const int tid = threadIdx.x, wid = tid >> 5, lane = tid & 31;
    const int row0 = blockIdx.x * 128;
    const float* __restrict__ X =
        (SRCSEL == 0) ? Xext : (SRCSEL == 1 ? (const float*)g_act : (const float*)g_hp);

    const int m0 = (wid >> 1) * 32;
    const int n0 = (wid & 1) * (NC / 2);
    const int gid = lane >> 2, tid4 = lane & 3;

    float acc[2][NPW][4];
#pragma unroll
    for (int mi = 0; mi < 2; mi++)
#pragma unroll
        for (int ni = 0; ni < NPW; ni++)
#pragma unroll
            for (int j = 0; j < 4; j++) acc[mi][ni][j] = 0.f;

    for (int kc = 0; kc < K; kc += 64) {
        if (kc) __syncthreads();
#pragma unroll
        for (int it = 0; it < 8; it++) {
            int i = tid + it * 256;
            int r = i >> 4, q = (i & 15) * 4;
            float4 v = make_float4(0.f, 0.f, 0.f, 0.f);
            if (row0 + r < N_NODES)
                v = *reinterpret_cast<const float4*>(X + (size_t)(row0 + r) * K + kc + q);
            __nv_bfloat16 h0, h1, h2, h3, l0, l1, l2, l3;
            split2(v.x, h0, l0); split2(v.y, h1, l1);
            split2(v.z, h2, l2); split2(v.w, h3, l3);
            *reinterpret_cast<uint2*>(As_hi + r * LDA + q) =
                make_uint2(pack_bf16x2(h0, h1), pack_bf16x2(h2, h3));
            *reinterpret_cast<uint2*>(As_lo + r * LDA + q) =
                make_uint2(pack_bf16x2(l0, l1), pack_bf16x2(l2, l3));
        }
#pragma unroll
        for (int it = 0; it < NC / 16; it++) {
            int i = tid + it * 256;
            int n = i % NC, q = (i / NC) * 4;
            float w0 = W[(size_t)(kc + q + 0) * NC + n];
            float w1 = W[(size_t)(kc + q + 1) * NC + n];
            float w2 = W[(size_t)(kc + q + 2) * NC + n];
            float w3 = W[(size_t)(kc + q + 3) * NC + n];
            __nv_bfloat16 h0, h1, h2, h3, l0, l1, l2, l3;
            split2(w0, h0, l0); split2(w1, h1, l1);
            split2(w2, h2, l2); split2(w3, h3, l3);
            *reinterpret_cast<uint2*>(Bs_hi + n * LDA + q) =
                make_uint2(pack_bf16x2(h0, h1), pack_bf16x2(h2, h3));
            *reinterpret_cast<uint2*>(Bs_lo + n * LDA + q) =
                make_uint2(pack_bf16x2(l0, l1), pack_bf16x2(l2, l3));
        }
        __syncthreads();

#pragma unroll
        for (int k16 = 0; k16 < 64; k16 += 16) {
            uint32_t bh[NPW][2], bl[NPW][2];
#pragma unroll
            for (int ni = 0; ni < NPW; ni++) {
                const __nv_bfloat16* bp = Bs_hi + (n0 + ni * 8 + gid) * LDA + k16 + tid4 * 2;
                const __nv_bfloat16* bq = Bs_lo + (n0 + ni * 8 + gid) * LDA + k16 + tid4 * 2;
                bh[ni][0] = *reinterpret_cast<const uint32_t*>(bp);
                bh[ni][1] = *reinterpret_cast<const uint32_t*>(bp + 8);
                bl[ni][0] = *reinterpret_cast<const uint32_t*>(bq);
                bl[ni][1] = *reinterpret_cast<const uint32_t*>(bq + 8);
            }
#pragma unroll
            for (int mi = 0; mi < 2; mi++) {
                const int r = m0 + mi * 16 + gid;
                const int c = k16 + tid4 * 2;
                uint32_t ah[4], al[4];
                ah[0] = *reinterpret_cast<const uint32_t*>(As_hi + r * LDA + c);
                ah[1] = *reinterpret_cast<const uint32_t*>(As_hi + (r + 8) * LDA + c);
                ah[2] = *reinterpret_cast<const uint32_t*>(As_hi + r * LDA + c + 8);
                ah[3] = *reinterpret_cast<const uint32_t*>(As_hi + (r + 8) * LDA + c + 8);
                al[0] = *reinterpret_cast<const uint32_t*>(As_lo + r * LDA + c);
                al[1] = *reinterpret_cast<const uint32_t*>(As_lo + (r + 8) * LDA + c);
                al[2] = *reinterpret_cast<const uint32_t*>(As_lo + r * LDA + c + 8);
                al[3] = *reinterpret_cast<const uint32_t*>(As_lo + (r + 8) * LDA + c + 8);
#pragma unroll
                for (int ni = 0; ni < NPW; ni++) {
                    mma16816(acc[mi][ni], ah, bh[ni]);
                    mma16816(acc[mi][ni], ah, bl[ni]);
                    mma16816(acc[mi][ni], al, bh[ni]);
                }
            }
        }
    }

    // ---- epilogue ----
#pragma unroll
    for (int mi = 0; mi < 2; mi++) {
#pragma unroll
        for (int rr = 0; rr < 2; rr++) {
            int r = row0 + m0 + mi * 16 + gid + rr * 8;
            if (r < N_NODES) {
#pragma unroll
                for (int ni = 0; ni < NPW; ni++) {
                    int cn = n0 + ni * 8 + tid4 * 2;
                    float c0 = acc[mi][ni][rr * 2 + 0];
                    float c1 = acc[mi][ni][rr * 2 + 1];
                    if (EPI == 0) {
                        float d = g_dinv[r];
                        __half2 o = __floats2half2_rn(c0 * d, c1 * d);
                        *reinterpret_cast<__half2*>(g_hp16 + (size_t)r * HID + cn) = o;
                    } else {
                        float2 bb = *reinterpret_cast<const float2*>(bias + cn);
                        float2 o;
                        if (EPI == 1) {
                            o.x = fmaxf(c0 + bb.x, 0.f);
                            o.y = fmaxf(c1 + bb.y, 0.f);
                            *reinterpret_cast<float2*>(g_hp + (size_t)r * HID + cn) = o;
                        } else {
                            o.x = c0 + bb.x; o.y = c1 + bb.y;
                            *reinterpret_cast<float2*>(outext + (size_t)r * OUTD + cn) = o;
                        }
                    }
                }
            }
        }
    }
}

// ---------------- CSR aggregation (fp16 gather) + BN + ReLU (warp per dst) -------
__global__ __launch_bounds__(256) void agg_bn_kernel(const float* __restrict__ bias,
                                                     const float* __restrict__ gam,
                                                     const float* __restrict__ bet,
                                                     const float* __restrict__ mu,
                                                     const float* __restrict__ var) {
    int n = (blockIdx.x * 256 + threadIdx.x) >> 5;
    int lane = threadIdx.x & 31;
    if (n >= N_NODES) return;

    // lane handles 4 channels: [lane*4, lane*4+4)
    const __half* hp = g_hp16;
    float4 acc;
    {
        uint2 u = *reinterpret_cast<const uint2*>(hp + (size_t)n * HID + lane * 4);
        float2 f0 = __half22float2(*reinterpret_cast<__half2*>(&u.x));
        float2 f1 = __half22float2(*reinterpret_cast<__half2*>(&u.y));
        acc = make_float4(f0.x, f0.y, f1.x, f1.y);
    }

    int e = g_rowptr[n];
    const int e1 = g_rowptr[n + 1];
    for (; e + 8 <= e1; e += 8) {
        int s[8];
#pragma unroll
        for (int j = 0; j < 8; j++) s[j] = g_colidx[e + j];
        uint2 u[8];
#pragma unroll
        for (int j = 0; j < 8; j++)
            u[j] = *reinterpret_cast<const uint2*>(hp + (size_t)s[j] * HID + lane * 4);
#pragma unroll
        for (int j = 0; j < 8; j++) {
            float2 f0 = __half22float2(*reinterpret_cast<__half2*>(&u[j].x));
            float2 f1 = __half22float2(*reinterpret_cast<__half2*>(&u[j].y));
            acc.x += f0.x; acc.y += f0.y; acc.z += f1.x; acc.w += f1.y;
        }
    }
    for (; e < e1; e++) {
        int s = g_colidx[e];
        uint2 u = *reinterpret_cast<const uint2*>(hp + (size_t)s * HID + lane * 4);
        float2 f0 = __half22float2(*reinterpret_cast<__half2*>(&u.x));
        float2 f1 = __half22float2(*reinterpret_cast<__half2*>(&u.y));
        acc.x += f0.x; acc.y += f0.y; acc.z += f1.x; acc.w += f1.y;
    }

    const float d = g_dinv[n];
    float4 gg = reinterpret_cast<const float4*>(gam)[lane];
    float4 vv = reinterpret_cast<const float4*>(var)[lane];
    float4 mm = reinterpret_cast<const float4*>(mu)[lane];
    float4 be = reinterpret_cast<const float4*>(bet)[lane];
    float4 bb = reinterpret_cast<const float4*>(bias)[lane];
    float4 o;
    {
        float s;
        s = gg.x * rsqrtf(vv.x + BN_EPS); o.x = fmaxf((d * acc.x + bb.x - mm.x) * s + be.x, 0.f);
        s = gg.y * rsqrtf(vv.y + BN_EPS); o.y = fmaxf((d * acc.y + bb.y - mm.y) * s + be.y, 0.f);
        s = gg.z * rsqrtf(vv.z + BN_EPS); o.z = fmaxf((d * acc.z + bb.z - mm.z) * s + be.z, 0.f);
        s = gg.w * rsqrtf(vv.w + BN_EPS); o.w = fmaxf((d * acc.w + bb.w - mm.w) * s + be.w, 0.f);
    }
    reinterpret_cast<float4*>(g_act + (size_t)n * HID)[lane] = o;
}

// ---------------- launch ----------------
extern "C" void kernel_launch(void* const* d_in, const int* in_sizes, int n_in,
                              void* d_out, int out_size) {
    (void)in_sizes; (void)n_in; (void)out_size;
    const float* x   = (const float*)d_in[0];
    const int*   src = (const int*)d_in[1];
    const int*   dst = (const int*)d_in[2];
    const float* W0 = (const float*)d_in[3],  *b0 = (const float*)d_in[4];
    const float* g0 = (const float*)d_in[5],  *be0 = (const float*)d_in[6];
    const float* m0 = (const float*)d_in[7],  *v0 = (const float*)d_in[8];
    const float* W1 = (const float*)d_in[9],  *b1 = (const float*)d_in[10];
    const float* g1 = (const float*)d_in[11], *be1 = (const float*)d_in[12];
    const float* m1 = (const float*)d_in[13], *v1 = (const float*)d_in[14];
    const float* W2 = (const float*)d_in[15], *b2 = (const float*)d_in[16];
    const float* g2 = (const float*)d_in[17], *be2 = (const float*)d_in[18];
    const float* m2 = (const float*)d_in[19], *v2 = (const float*)d_in[20];
    const float* Wm1 = (const float*)d_in[21], *bm1 = (const float*)d_in[22];
    const float* Wm2 = (const float*)d_in[23], *bm2 = (const float*)d_in[24];
    float* out = (float*)d_out;

    const int NB_NODE = (N_NODES + 255) / 256;
    const int NB_EDGE = (N_EDGES + 255) / 256;
    const int NB_GEMM = (N_NODES + 127) / 128;
    const int NB_AGG  = (N_NODES + 7) / 8;

    constexpr int SM_128 = (2 * 128 + 2 * 128) * 72 * 2;  // 73728
    constexpr int SM_64  = (2 * 128 + 2 * 64) * 72 * 2;   // 55296

    cudaFuncSetAttribute(mma_gemm_kernel<64, 128, 0, 0>,
                         cudaFuncAttributeMaxDynamicSharedMemorySize, SM_128);
    cudaFuncSetAttribute(mma_gemm_kernel<128, 128, 1, 0>,
                         cudaFuncAttributeMaxDynamicSharedMemorySize, SM_128);
    cudaFuncSetAttribute(mma_gemm_kernel<128, 128, 1, 1>,
                         cudaFuncAttributeMaxDynamicSharedMemorySize, SM_128);
    cudaFuncSetAttribute(mma_gemm_kernel<128, 64, 2, 2>,
                         cudaFuncAttributeMaxDynamicSharedMemorySize, SM_64);

    // CSR + dinv
    zero_cnt_kernel<<<NB_NODE, 256>>>();
    hist_kernel<<<NB_EDGE, 256>>>(dst);
    scan_dinv_kernel<<<1, 1024>>>();
    fill_csr_kernel<<<NB_EDGE, 256>>>(src, dst);

    // layer 0
    mma_gemm_kernel<64, 128, 0, 0><<<NB_GEMM, 256, SM_128>>>(x, W0, nullptr, nullptr);
    agg_bn_kernel<<<NB_AGG, 256>>>(b0, g0, be0, m0, v0);
    // layer 1
    mma_gemm_kernel<128, 128, 1, 0><<<NB_GEMM, 256, SM_128>>>(nullptr, W1, nullptr, nullptr);
    agg_bn_kernel<<<NB_AGG, 256>>>(b1, g1, be1, m1, v1);
    // layer 2
    mma_gemm_kernel<128, 128, 1, 0><<<NB_GEMM, 256, SM_128>>>(nullptr, W2, nullptr, nullptr);
    agg_bn_kernel<<<NB_AGG, 256>>>(b2, g2, be2, m2, v2);

    // MLP head
    mma_gemm_kernel<128, 128, 1, 1><<<NB_GEMM, 256, SM_128>>>(nullptr, Wm1, bm1, nullptr);
    mma_gemm_kernel<128, 64, 2, 2><<<NB_GEMM, 256, SM_64>>>(nullptr, Wm2, bm2, out);
}